// round 7
// baseline (speedup 1.0000x reference)
#include <cuda_runtime.h>
#include <cstdint>
#include <cstddef>

// Problem constants
#define NEXP 8
#define TOPK 2
#define DIM 1024
#define DFF 4096
#define NTOK 16384          // B*S = 4*4096
#define CAP  16384          // per-expert capacity (worst case all tokens)
#define RTOT (NTOK * TOPK)  // 32768 total expert-rows

// ---------------- scratch (static device globals; no runtime alloc) ----------
// NOTE: these are ONLY ever referenced from device code. Passing a __device__
// symbol as a host-side kernel argument resolves to the host shadow variable
// (silently readable via ATS on GB300 -> zeros), which is what broke R2-R5.
__device__ int   g_cnt[NEXP];
__device__ int   g_off[NEXP];
__device__ int   g_tok[NEXP * CAP];
__device__ int   g_dst[NEXP * CAP];
__device__ float g_wtl[NEXP * CAP];
__device__ float g_H[(size_t)RTOT * DFF];   // 512 MB hidden scratch
__device__ float g_O[(size_t)RTOT * DIM];   // 128 MB per-slot outputs

// ---------------- helpers ----------------------------------------------------
__device__ __forceinline__ float tf32r(float f) {
    unsigned u;
    asm volatile("cvt.rna.tf32.f32 %0, %1;" : "=r"(u) : "f"(f));
    return __uint_as_float(u);
}

__device__ __forceinline__ void mma_tf32(float c[4], const unsigned a[4], const unsigned b[2]) {
    asm volatile(
        "mma.sync.aligned.m16n8k8.row.col.f32.tf32.tf32.f32 "
        "{%0,%1,%2,%3}, {%4,%5,%6,%7}, {%8,%9}, {%0,%1,%2,%3};\n"
        : "+f"(c[0]), "+f"(c[1]), "+f"(c[2]), "+f"(c[3])
        : "r"(a[0]), "r"(a[1]), "r"(a[2]), "r"(a[3]), "r"(b[0]), "r"(b[1]));
}

// ---------------- kernel 0: zero counters ------------------------------------
__global__ void zero_kernel() {
    if (threadIdx.x < NEXP) g_cnt[threadIdx.x] = 0;
}

// ---------------- kernel 1: routing (one warp per token) ----------------------
__global__ void route_kernel(const float* __restrict__ x, const float* __restrict__ gw) {
    __shared__ float s_gw[NEXP * DIM];   // 32 KB
    int tid = threadIdx.x;
    for (int i = tid; i < NEXP * DIM; i += blockDim.x) s_gw[i] = gw[i];
    __syncthreads();

    int warp = tid >> 5, lane = tid & 31;
    int t = blockIdx.x * (blockDim.x >> 5) + warp;
    if (t >= NTOK) return;

    const float* xr = x + (size_t)t * DIM;
    float xv[32];
#pragma unroll
    for (int i = 0; i < 32; i++) xv[i] = xr[i * 32 + lane];

    float logit[NEXP];
#pragma unroll
    for (int e = 0; e < NEXP; e++) {
        float acc = 0.f;
#pragma unroll
        for (int i = 0; i < 32; i++) acc += xv[i] * s_gw[e * DIM + i * 32 + lane];
#pragma unroll
        for (int o = 16; o; o >>= 1) acc += __shfl_xor_sync(0xffffffffu, acc, o);
        logit[e] = acc;
    }

    if (lane == 0) {
        // top-2, jax tie semantics: first occurrence of max wins
        int i0 = 0;
#pragma unroll
        for (int e = 1; e < NEXP; e++) if (logit[e] > logit[i0]) i0 = e;
        int i1 = (i0 == 0) ? 1 : 0;
#pragma unroll
        for (int e = 0; e < NEXP; e++) {
            if (e == i0 || e == i1) continue;
            if (logit[e] > logit[i1]) i1 = e;
        }
        float dd = logit[i1] - logit[i0];   // <= 0
        float ee = __expf(dd);
        float inv = 1.f / (1.f + ee);
        float w0 = inv, w1 = ee * inv;

        int p0 = atomicAdd(&g_cnt[i0], 1);
        g_tok[i0 * CAP + p0] = t;
        g_dst[i0 * CAP + p0] = t * 2;
        g_wtl[i0 * CAP + p0] = w0;
        int p1 = atomicAdd(&g_cnt[i1], 1);
        g_tok[i1 * CAP + p1] = t;
        g_dst[i1 * CAP + p1] = t * 2 + 1;
        g_wtl[i1 * CAP + p1] = w1;
    }
}

// ---------------- kernel 2: prefix offsets ------------------------------------
__global__ void prefix_kernel() {
    if (threadIdx.x == 0) {
        int s = 0;
#pragma unroll
        for (int e = 0; e < NEXP; e++) { g_off[e] = s; s += g_cnt[e]; }
    }
}

// ---------------- kernels 3/4: grouped GEMM, double-buffered (tf32 mma.sync) --
// MODE 0: H[off+m] = silu(gather(x)[m] @ W1[e] + b1[e])   (KDIM=DIM,  NDIM=DFF)
//         A source = Xin (harness pointer), gathered via g_tok.
// MODE 1: O[dst]   = (H[off+m] @ W2[e] + b2[e]) * wt      (KDIM=DFF,  NDIM=DIM)
//         A source = g_H, referenced FROM DEVICE CODE (Xin ignored).
template <int KDIM, int NDIM, int MODE>
__global__ void __launch_bounds__(256, 2) ffn_gemm(const float* __restrict__ Xin,
                                                   const float* __restrict__ Wall,
                                                   const float* __restrict__ ball) {
    constexpr int BM = 128, BN = 128, BK = 16;
    constexpr int APAD = 4, BPAD = 4;
    constexpr int KT = KDIM / BK;
    constexpr int NN = NDIM / BN;
    constexpr int GM = 8;                       // raster group (L2 reuse)

    // double-buffered static shared: 2 * (128*20 + 16*132) * 4 = 37,376 B
    __shared__ float sAb[2][BM][BK + APAD];
    __shared__ float sBb[2][BK][BN + BPAD];

    int e = blockIdx.z;
    int cnt = g_cnt[e];

    // grouped raster: m fast within group of GM, then n, then group
    int per = GM * NN;
    int grp = blockIdx.x / per;
    int rem = blockIdx.x - grp * per;
    int mb = grp * GM + (rem % GM);
    int nb = rem / GM;
    int m0 = mb * BM;
    if (m0 >= cnt) return;
    int n0 = nb * BN;
    int off = g_off[e];

    const float* W = Wall + (size_t)e * KDIM * NDIM + n0;
    const float* bias = ball + (size_t)e * NDIM;

    int tid = threadIdx.x;
    int warp = tid >> 5, lane = tid & 31;
    int wm = warp & 1, wn = warp >> 1;           // 2 (M) x 4 (N) warps; warp tile 64x32
    int group = lane >> 2, tig = lane & 3;

    // staging maps (16B chunks): A = 128x4 chunks, B = 16x32 chunks, 2 each/thread
    const float* a_src[2];
    bool aval[2];
    int a_r[2], a_c4[2];
#pragma unroll
    for (int i = 0; i < 2; i++) {
        int chunk = tid + 256 * i;
        int r = chunk >> 2, c4 = chunk & 3;
        a_r[i] = r; a_c4[i] = c4;
        int m = m0 + r;
        aval[i] = (m < cnt);
        if (MODE == 0) {
            int tok = aval[i] ? g_tok[e * CAP + m] : 0;
            a_src[i] = Xin + (size_t)tok * KDIM + c4 * 4;
        } else {
            int gr = aval[i] ? (off + m) : 0;
            a_src[i] = g_H + (size_t)gr * KDIM + c4 * 4;   // device-side symbol ref
        }
    }
    const float* b_src[2];
    int b_r[2], b_c4[2];
#pragma unroll
    for (int i = 0; i < 2; i++) {
        int chunk = tid + 256 * i;
        int r = chunk >> 5, c4 = chunk & 31;
        b_r[i] = r; b_c4[i] = c4;
        b_src[i] = W + (size_t)r * NDIM + c4 * 4;
    }

    float4 ra[2], rb[2];
    auto gload = [&](int kt) {
#pragma unroll
        for (int i = 0; i < 2; i++)
            ra[i] = aval[i] ? *(const float4*)(a_src[i] + (size_t)kt * BK)
                            : make_float4(0.f, 0.f, 0.f, 0.f);
#pragma unroll
        for (int i = 0; i < 2; i++)
            rb[i] = *(const float4*)(b_src[i] + (size_t)kt * BK * NDIM);
    };
    auto sstore = [&](int buf) {
#pragma unroll
        for (int i = 0; i < 2; i++) {
            float4 v = ra[i];
            v.x = tf32r(v.x); v.y = tf32r(v.y); v.z = tf32r(v.z); v.w = tf32r(v.w);
            *(float4*)&sAb[buf][a_r[i]][a_c4[i] * 4] = v;
        }
#pragma unroll
        for (int i = 0; i < 2; i++) {
            float4 v = rb[i];
            v.x = tf32r(v.x); v.y = tf32r(v.y); v.z = tf32r(v.z); v.w = tf32r(v.w);
            *(float4*)&sBb[buf][b_r[i]][b_c4[i] * 4] = v;
        }
    };

    float acc[4][4][4];
#pragma unroll
    for (int mi = 0; mi < 4; mi++)
#pragma unroll
        for (int ni = 0; ni < 4; ni++)
#pragma unroll
            for (int r = 0; r < 4; r++) acc[mi][ni][r] = 0.f;

    // prologue
    gload(0);
    sstore(0);
    gload(1);
    __syncthreads();

    for (int kt = 0; kt < KT; kt++) {
        if (kt + 1 < KT) sstore((kt + 1) & 1);   // other buffer; its last reads were
                                                 // fenced by the sync ending iter kt-1
        if (kt + 2 < KT) gload(kt + 2);          // refill regs; latency spans compute

        const float (*sA)[BK + APAD] = sAb[kt & 1];
        const float (*sB)[BN + BPAD] = sBb[kt & 1];
#pragma unroll
        for (int ks = 0; ks < 2; ks++) {
            int kk = ks * 8;
            unsigned af[4][4], bf[4][2];
#pragma unroll
            for (int mi = 0; mi < 4; mi++) {
                int r = wm * 64 + mi * 16 + group;
                af[mi][0] = __float_as_uint(sA[r][kk + tig]);
                af[mi][1] = __float_as_uint(sA[r + 8][kk + tig]);
                af[mi][2] = __float_as_uint(sA[r][kk + tig + 4]);
                af[mi][3] = __float_as_uint(sA[r + 8][kk + tig + 4]);
            }
#pragma unroll
            for (int ni = 0; ni < 4; ni++) {
                int c = wn * 32 + ni * 8 + group;
                bf[ni][0] = __float_as_uint(sB[kk + tig][c]);
                bf[ni][1] = __float_as_uint(sB[kk + tig + 4][c]);
            }
#pragma unroll
            for (int mi = 0; mi < 4; mi++)
#pragma unroll
                for (int ni = 0; ni < 4; ni++)
                    mma_tf32(acc[mi][ni], af[mi], bf[ni]);
        }
        __syncthreads();
    }

    // epilogue (identical to round-1 numerics)
#pragma unroll
    for (int mi = 0; mi < 4; mi++) {
#pragma unroll
        for (int half = 0; half < 2; half++) {
            int m = m0 + wm * 64 + mi * 16 + group + half * 8;
            if (m >= cnt) continue;
            if (MODE == 0) {
                size_t rowbase = (size_t)(off + m) * NDIM;
#pragma unroll
                for (int ni = 0; ni < 4; ni++) {
                    int c = n0 + wn * 32 + ni * 8 + tig * 2;
                    float v0 = acc[mi][ni][half * 2 + 0] + bias[c];
                    float v1 = acc[mi][ni][half * 2 + 1] + bias[c + 1];
                    g_H[rowbase + c]     = v0 / (1.f + __expf(-v0));
                    g_H[rowbase + c + 1] = v1 / (1.f + __expf(-v1));
                }
            } else {
                int dst = g_dst[e * CAP + m];
                float w = g_wtl[e * CAP + m];
                size_t rowbase = (size_t)dst * NDIM;
#pragma unroll
                for (int ni = 0; ni < 4; ni++) {
                    int c = n0 + wn * 32 + ni * 8 + tig * 2;
                    g_O[rowbase + c]     = (acc[mi][ni][half * 2 + 0] + bias[c]) * w;
                    g_O[rowbase + c + 1] = (acc[mi][ni][half * 2 + 1] + bias[c + 1]) * w;
                }
            }
        }
    }
}

// ---------------- kernel 5: combine the two slots -----------------------------
__global__ void combine_kernel(float4* __restrict__ out) {
    int i = blockIdx.x * 256 + threadIdx.x;       // one float4 each; exact cover
    int t = i >> 8;                               // DIM/4 = 256 float4 per token
    int d4 = i & 255;
    const float4* O4 = (const float4*)g_O;        // device-side symbol ref
    float4 a = O4[(size_t)(2 * t) * 256 + d4];
    float4 b = O4[(size_t)(2 * t + 1) * 256 + d4];
    out[i] = make_float4(a.x + b.x, a.y + b.y, a.z + b.z, a.w + b.w);
}

// ---------------- launch ------------------------------------------------------
extern "C" void kernel_launch(void* const* d_in, const int* in_sizes, int n_in,
                              void* d_out, int out_size) {
    const float* x  = (const float*)d_in[0];
    const float* gw = (const float*)d_in[1];
    const float* W1 = (const float*)d_in[2];
    const float* b1 = (const float*)d_in[3];
    const float* W2 = (const float*)d_in[4];
    const float* b2 = (const float*)d_in[5];
    float* out = (float*)d_out;

    zero_kernel<<<1, 32>>>();
    route_kernel<<<NTOK / 8, 256>>>(x, gw);
    prefix_kernel<<<1, 32>>>();

    // GEMM1: grid.x = (CAP/128 m-blocks) * (DFF/128 n-blocks), z = experts
    ffn_gemm<DIM, DFF, 0><<<dim3((CAP / 128) * (DFF / 128), 1, NEXP), 256>>>(x, W1, b1);
    // GEMM2: A comes from g_H inside the kernel; x arg is ignored (NEVER pass
    // a __device__ symbol from host — it resolves to the host shadow).
    ffn_gemm<DFF, DIM, 1><<<dim3((CAP / 128) * (DIM / 128), 1, NEXP), 256>>>(x, W2, b2);

    combine_kernel<<<(NTOK * (DIM / 4)) / 256, 256>>>((float4*)out);
}

// round 8
// speedup vs baseline: 1.9127x; 1.9127x over previous
#include <cuda_runtime.h>
#include <cstdint>
#include <cstddef>

// Problem constants
#define NEXP 8
#define TOPK 2
#define DIM 1024
#define DFF 4096
#define NTOK 16384          // B*S = 4*4096
#define CAP  16384          // per-expert capacity (worst case all tokens)
#define RTOT (NTOK * TOPK)  // 32768 total expert-rows
#define PADR 128            // row padding for tile overrun

// ---------------- scratch (static device globals; no runtime alloc) ----------
// RULE (cost: rounds 2-5): NEVER pass these symbols as host-side kernel args.
// The host shadow is ATS-readable on GB300 and reads as zeros. All references
// below are from device code only.
__device__ int   g_cnt[NEXP];
__device__ int   g_off[NEXP];
__device__ int   g_tok[NEXP * CAP];
__device__ int   g_dst[NEXP * CAP];
__device__ float g_wtl[NEXP * CAP];
__device__ float g_Xg[(size_t)(RTOT + PADR) * DIM];   // gathered + tf32-rounded x
__device__ float g_H[(size_t)(RTOT + PADR) * DFF];    // hidden scratch (tf32-rounded)
__device__ float g_O[(size_t)RTOT * DIM];             // per-slot outputs
__device__ float g_W1r[(size_t)NEXP * DIM * DFF];     // tf32-rounded W1
__device__ float g_W2r[(size_t)NEXP * DFF * DIM];     // tf32-rounded W2

// ---------------- helpers ----------------------------------------------------
__device__ __forceinline__ float tf32r(float f) {
    unsigned u;
    asm volatile("cvt.rna.tf32.f32 %0, %1;" : "=r"(u) : "f"(f));
    return __uint_as_float(u);
}

__device__ __forceinline__ void mma_tf32(float c[4], const unsigned a[4], const unsigned b[2]) {
    asm volatile(
        "mma.sync.aligned.m16n8k8.row.col.f32.tf32.tf32.f32 "
        "{%0,%1,%2,%3}, {%4,%5,%6,%7}, {%8,%9}, {%0,%1,%2,%3};\n"
        : "+f"(c[0]), "+f"(c[1]), "+f"(c[2]), "+f"(c[3])
        : "r"(a[0]), "r"(a[1]), "r"(a[2]), "r"(a[3]), "r"(b[0]), "r"(b[1]));
}

__device__ __forceinline__ void cpasync16(uint32_t d, const void* s) {
    asm volatile("cp.async.cg.shared.global [%0], [%1], 16;" :: "r"(d), "l"(s));
}
__device__ __forceinline__ void cp_commit() {
    asm volatile("cp.async.commit_group;");
}
template <int N>
__device__ __forceinline__ void cp_wait() {
    asm volatile("cp.async.wait_group %0;" :: "n"(N));
}

// ---------------- kernel 0: zero counters ------------------------------------
__global__ void zero_kernel() {
    if (threadIdx.x < NEXP) g_cnt[threadIdx.x] = 0;
}

// ---------------- kernel 1: routing (one warp per token) ----------------------
__global__ void route_kernel(const float* __restrict__ x, const float* __restrict__ gw) {
    __shared__ float s_gw[NEXP * DIM];   // 32 KB
    int tid = threadIdx.x;
    for (int i = tid; i < NEXP * DIM; i += blockDim.x) s_gw[i] = gw[i];
    __syncthreads();

    int warp = tid >> 5, lane = tid & 31;
    int t = blockIdx.x * (blockDim.x >> 5) + warp;
    if (t >= NTOK) return;

    const float* xr = x + (size_t)t * DIM;
    float xv[32];
#pragma unroll
    for (int i = 0; i < 32; i++) xv[i] = xr[i * 32 + lane];

    float logit[NEXP];
#pragma unroll
    for (int e = 0; e < NEXP; e++) {
        float acc = 0.f;
#pragma unroll
        for (int i = 0; i < 32; i++) acc += xv[i] * s_gw[e * DIM + i * 32 + lane];
#pragma unroll
        for (int o = 16; o; o >>= 1) acc += __shfl_xor_sync(0xffffffffu, acc, o);
        logit[e] = acc;
    }

    if (lane == 0) {
        // top-2, jax tie semantics: first occurrence of max wins
        int i0 = 0;
#pragma unroll
        for (int e = 1; e < NEXP; e++) if (logit[e] > logit[i0]) i0 = e;
        int i1 = (i0 == 0) ? 1 : 0;
#pragma unroll
        for (int e = 0; e < NEXP; e++) {
            if (e == i0 || e == i1) continue;
            if (logit[e] > logit[i1]) i1 = e;
        }
        float dd = logit[i1] - logit[i0];   // <= 0
        float ee = __expf(dd);
        float inv = 1.f / (1.f + ee);
        float w0 = inv, w1 = ee * inv;

        int p0 = atomicAdd(&g_cnt[i0], 1);
        g_tok[i0 * CAP + p0] = t;
        g_dst[i0 * CAP + p0] = t * 2;
        g_wtl[i0 * CAP + p0] = w0;
        int p1 = atomicAdd(&g_cnt[i1], 1);
        g_tok[i1 * CAP + p1] = t;
        g_dst[i1 * CAP + p1] = t * 2 + 1;
        g_wtl[i1 * CAP + p1] = w1;
    }
}

// ---------------- kernel 2: prefix offsets ------------------------------------
__global__ void prefix_kernel() {
    if (threadIdx.x == 0) {
        int s = 0;
#pragma unroll
        for (int e = 0; e < NEXP; e++) { g_off[e] = s; s += g_cnt[e]; }
    }
}

// ---------------- kernel 3: round weights to tf32 (dst chosen in device code) -
template <int WHICH>
__global__ void roundcpy_kernel(const float4* __restrict__ src, int n4) {
    float4* dst = (float4*)(WHICH == 0 ? g_W1r : g_W2r);   // device-side symbol
    int i = blockIdx.x * blockDim.x + threadIdx.x;
#pragma unroll
    for (int r = 0; r < 2; r++) {
        int idx = i + r * (gridDim.x * blockDim.x);
        if (idx < n4) {
            float4 v = src[idx];
            v.x = tf32r(v.x); v.y = tf32r(v.y); v.z = tf32r(v.z); v.w = tf32r(v.w);
            dst[idx] = v;
        }
    }
}

// ---------------- kernel 4: gather + round x ----------------------------------
__global__ void gather_kernel(const float* __restrict__ x) {
    int e = blockIdx.y, m = blockIdx.x;
    if (m >= g_cnt[e]) return;
    int tok = g_tok[e * CAP + m];
    int row = g_off[e] + m;
    const float4* src = (const float4*)(x + (size_t)tok * DIM);
    float4* dst = (float4*)(g_Xg + (size_t)row * DIM);     // device-side symbol
    float4 v = src[threadIdx.x];
    v.x = tf32r(v.x); v.y = tf32r(v.y); v.z = tf32r(v.z); v.w = tf32r(v.w);
    dst[threadIdx.x] = v;
}

// ---------------- kernels 5/6: cp.async pipelined grouped GEMM ----------------
// MODE 0: H[off+m] = silu(Xg[off+m] @ W1r[e] + b1[e])   (KDIM=DIM,  NDIM=DFF)
// MODE 1: O[dst]   = (H[off+m] @ W2r[e] + b2[e]) * wt   (KDIM=DFF,  NDIM=DIM)
// A and W are selected INSIDE the kernel from device symbols (MODE).
template <int KDIM, int NDIM, int MODE>
__global__ void __launch_bounds__(256, 1) ffn_gemm(const float* __restrict__ ball) {
    constexpr int BM = 128, BN = 256, BK = 32, STAGES = 3;
    constexpr int APAD = 4, BPAD = 8;
    constexpr int SA = BM * (BK + APAD);        // 4608 floats
    constexpr int SB = BK * (BN + BPAD);        // 8448 floats
    constexpr int SS = SA + SB;                 // floats per stage
    constexpr int KT = KDIM / BK;
    constexpr int NN = NDIM / BN;
    constexpr int GM = 16;                      // raster group (L2 reuse)

    extern __shared__ float sm[];

    const float* Ain  = (MODE == 0) ? g_Xg : g_H;                 // device symbols
    const float* Wall = (MODE == 0) ? g_W1r : g_W2r;

    int e = blockIdx.z;
    int cnt = g_cnt[e];

    // grouped raster: within a group of per=GM*NN CTAs, mb fast, then nb.
    int per = GM * NN;
    int grp = blockIdx.x / per;
    int rem = blockIdx.x - grp * per;
    int mb = grp * GM + (rem % GM);
    int nb = rem / GM;
    int m0 = mb * BM;
    if (m0 >= cnt) return;
    int n0 = nb * BN;
    int off = g_off[e];

    const float* Abase = Ain + (size_t)(off + m0) * KDIM;
    const float* W = Wall + (size_t)e * KDIM * NDIM + n0;
    const float* bias = ball + (size_t)e * NDIM;

    int tid = threadIdx.x;
    int warp = tid >> 5, lane = tid & 31;
    int wm = warp & 1, wn = warp >> 1;           // 2 (M) x 4 (N) warps; warp tile 64x64
    int group = lane >> 2, tig = lane & 3;

    uint32_t sbase = (uint32_t)__cvta_generic_to_shared(sm);

    // staging maps (16B chunks)
    const float* a_src[4];
    uint32_t a_dst[4];
#pragma unroll
    for (int i = 0; i < 4; i++) {
        int chunk = tid + 256 * i;               // 1024 chunks: 128 rows x 8
        int r = chunk >> 3, c4 = chunk & 7;
        a_src[i] = Abase + (size_t)r * KDIM + c4 * 4;
        a_dst[i] = (uint32_t)((r * (BK + APAD) + c4 * 4) * 4);
    }
    const float* b_src[8];
    uint32_t b_dst[8];
#pragma unroll
    for (int i = 0; i < 8; i++) {
        int chunk = tid + 256 * i;               // 2048 chunks: 32 rows x 64
        int r = chunk >> 6, c4 = chunk & 63;
        b_src[i] = W + (size_t)r * NDIM + c4 * 4;
        b_dst[i] = (uint32_t)((SA + r * (BN + BPAD) + c4 * 4) * 4);
    }

    auto issue = [&](int kt, int stage) {
        uint32_t sb = sbase + (uint32_t)(stage * SS * 4);
#pragma unroll
        for (int i = 0; i < 4; i++)
            cpasync16(sb + a_dst[i], a_src[i] + (size_t)kt * BK);
#pragma unroll
        for (int i = 0; i < 8; i++)
            cpasync16(sb + b_dst[i], b_src[i] + (size_t)kt * BK * NDIM);
    };

    float acc[4][8][4];
#pragma unroll
    for (int mi = 0; mi < 4; mi++)
#pragma unroll
        for (int ni = 0; ni < 8; ni++)
#pragma unroll
            for (int r = 0; r < 4; r++) acc[mi][ni][r] = 0.f;

    // prologue: prefetch STAGES-1 stages
    issue(0, 0); cp_commit();
    issue(1, 1); cp_commit();

    for (int kt = 0; kt < KT; kt++) {
        cp_wait<1>();
        __syncthreads();
        if (kt + 2 < KT) issue(kt + 2, (kt + 2) % STAGES);
        cp_commit();

        const float* sA = sm + (kt % STAGES) * SS;
        const float* sB = sA + SA;
#pragma unroll
        for (int ks = 0; ks < 4; ks++) {
            int kk = ks * 8;
            unsigned af[4][4], bf[8][2];
#pragma unroll
            for (int mi = 0; mi < 4; mi++) {
                int r = wm * 64 + mi * 16 + group;
                af[mi][0] = __float_as_uint(sA[r * (BK + APAD) + kk + tig]);
                af[mi][1] = __float_as_uint(sA[(r + 8) * (BK + APAD) + kk + tig]);
                af[mi][2] = __float_as_uint(sA[r * (BK + APAD) + kk + tig + 4]);
                af[mi][3] = __float_as_uint(sA[(r + 8) * (BK + APAD) + kk + tig + 4]);
            }
#pragma unroll
            for (int ni = 0; ni < 8; ni++) {
                int c = wn * 64 + ni * 8 + group;
                bf[ni][0] = __float_as_uint(sB[(kk + tig) * (BN + BPAD) + c]);
                bf[ni][1] = __float_as_uint(sB[(kk + tig + 4) * (BN + BPAD) + c]);
            }
#pragma unroll
            for (int mi = 0; mi < 4; mi++)
#pragma unroll
                for (int ni = 0; ni < 8; ni++)
                    mma_tf32(acc[mi][ni], af[mi], bf[ni]);
        }
        __syncthreads();
    }

    // epilogue (same rounding points as the green round-1/6 kernels)
#pragma unroll
    for (int mi = 0; mi < 4; mi++) {
#pragma unroll
        for (int half = 0; half < 2; half++) {
            int m = m0 + wm * 64 + mi * 16 + group + half * 8;
            if (m >= cnt) continue;
            if (MODE == 0) {
                size_t rowbase = (size_t)(off + m) * NDIM;
#pragma unroll
                for (int ni = 0; ni < 8; ni++) {
                    int c = n0 + wn * 64 + ni * 8 + tig * 2;
                    float v0 = acc[mi][ni][half * 2 + 0] + bias[c];
                    float v1 = acc[mi][ni][half * 2 + 1] + bias[c + 1];
                    g_H[rowbase + c]     = tf32r(v0 / (1.f + __expf(-v0)));
                    g_H[rowbase + c + 1] = tf32r(v1 / (1.f + __expf(-v1)));
                }
            } else {
                int dst = g_dst[e * CAP + m];
                float w = g_wtl[e * CAP + m];
                size_t rowbase = (size_t)dst * NDIM;
#pragma unroll
                for (int ni = 0; ni < 8; ni++) {
                    int c = n0 + wn * 64 + ni * 8 + tig * 2;
                    g_O[rowbase + c]     = (acc[mi][ni][half * 2 + 0] + bias[c]) * w;
                    g_O[rowbase + c + 1] = (acc[mi][ni][half * 2 + 1] + bias[c + 1]) * w;
                }
            }
        }
    }
}

// ---------------- kernel 7: combine the two slots -----------------------------
__global__ void combine_kernel(float4* __restrict__ out) {
    int i = blockIdx.x * 256 + threadIdx.x;       // one float4 each; exact cover
    int t = i >> 8;                               // DIM/4 = 256 float4 per token
    int d4 = i & 255;
    const float4* O4 = (const float4*)g_O;        // device-side symbol
    float4 a = O4[(size_t)(2 * t) * 256 + d4];
    float4 b = O4[(size_t)(2 * t + 1) * 256 + d4];
    out[i] = make_float4(a.x + b.x, a.y + b.y, a.z + b.z, a.w + b.w);
}

// ---------------- launch ------------------------------------------------------
extern "C" void kernel_launch(void* const* d_in, const int* in_sizes, int n_in,
                              void* d_out, int out_size) {
    const float* x  = (const float*)d_in[0];
    const float* gw = (const float*)d_in[1];
    const float* W1 = (const float*)d_in[2];
    const float* b1 = (const float*)d_in[3];
    const float* W2 = (const float*)d_in[4];
    const float* b2 = (const float*)d_in[5];
    float* out = (float*)d_out;

    // opt into >48KB dynamic smem (host attribute call; not an allocation)
    constexpr int GEMM_SMEM = 3 * (128 * 36 + 32 * 264) * 4;   // 156,672 B
    cudaFuncSetAttribute(ffn_gemm<DIM, DFF, 0>,
                         cudaFuncAttributeMaxDynamicSharedMemorySize, GEMM_SMEM);
    cudaFuncSetAttribute(ffn_gemm<DFF, DIM, 1>,
                         cudaFuncAttributeMaxDynamicSharedMemorySize, GEMM_SMEM);

    zero_kernel<<<1, 32>>>();
    route_kernel<<<NTOK / 8, 256>>>(x, gw);
    prefix_kernel<<<1, 32>>>();

    // pre-round weights to tf32 (harness pointers in, device symbols out)
    {
        int n4 = NEXP * DIM * DFF / 4;            // 8,388,608 float4
        roundcpy_kernel<0><<<16384, 256>>>((const float4*)W1, n4);
        roundcpy_kernel<1><<<16384, 256>>>((const float4*)W2, n4);
    }
    gather_kernel<<<dim3(CAP, NEXP), 256>>>(x);

    // GEMM1: grid.x = (CAP/128 m-blocks) * (DFF/256 n-blocks), z = experts
    ffn_gemm<DIM, DFF, 0><<<dim3((CAP / 128) * (DFF / 256), 1, NEXP), 256, GEMM_SMEM>>>(b1);
    // GEMM2
    ffn_gemm<DFF, DIM, 1><<<dim3((CAP / 128) * (DIM / 256), 1, NEXP), 256, GEMM_SMEM>>>(b2);

    combine_kernel<<<(NTOK * (DIM / 4)) / 256, 256>>>((float4*)out);
}